// round 1
// baseline (speedup 1.0000x reference)
#include <cuda_runtime.h>
#include <math.h>

#define Bsz 32768
#define Fn 16
#define Hn 64
#define On 32
#define En 16
#define BM 128

// ---------------- device scratch (no allocations allowed) ----------------
__device__ float g_tok[(size_t)Bsz * Fn * En];   // 33.5 MB: tok[B][F][E]
__device__ float g_W3p[Fn * Hn * En];            // fused W3[f] @ Wp
__device__ float g_b3p[Fn * En];                 // fused b3[f] @ Wp + bp

// ---------------- setup: fold W3@Wp and b3@Wp+bp ----------------
__global__ void k_setup(const float* __restrict__ W3, const float* __restrict__ b3,
                        const float* __restrict__ Wp, const float* __restrict__ bp) {
  int f = blockIdx.x;
  __shared__ float Wps[On * En];
  __shared__ float w3s[Hn * On];
  for (int i = threadIdx.x; i < On * En; i += blockDim.x) Wps[i] = Wp[i];
  for (int i = threadIdx.x; i < Hn * On; i += blockDim.x) w3s[i] = W3[f * Hn * On + i];
  __syncthreads();
  for (int idx = threadIdx.x; idx < Hn * En; idx += blockDim.x) {
    int h = idx / En, e = idx % En;
    float acc = 0.f;
    for (int o = 0; o < On; o++) acc += w3s[h * On + o] * Wps[o * En + e];
    g_W3p[f * Hn * En + idx] = acc;
  }
  for (int e = threadIdx.x; e < En; e += blockDim.x) {
    float acc = bp[e];
    for (int o = 0; o < On; o++) acc += b3[f * On + o] * Wps[o * En + e];
    g_b3p[f * En + e] = acc;
  }
}

// ---------------- pass 1: per-feature subnet -> tok ----------------
struct SM1 {
  float W2s[Hn][Hn];      // [h][k]  16 KB
  float h1T[Hn][BM];      // [h][row] 32 KB
  float h2T[Hn][BM];      // [k][row] 32 KB
  float W3ps[Hn][En];     // 4 KB
  float W1s[Hn];
  float b1s[Hn];
  float b2s[Hn];
  float b3ps[En];
  float xs[BM];
};

__device__ __forceinline__ float leaky(float v) { return v >= 0.f ? v : 0.01f * v; }

__global__ __launch_bounds__(256, 2) void k_subnet(
    const float* __restrict__ x, const float* __restrict__ W1,
    const float* __restrict__ b1, const float* __restrict__ W2,
    const float* __restrict__ b2) {
  extern __shared__ char smraw[];
  SM1& s = *reinterpret_cast<SM1*>(smraw);
  const int f = blockIdx.y;
  const int b0 = blockIdx.x * BM;
  const int tid = threadIdx.x;

  if (tid < Hn) {
    s.W1s[tid] = W1[f * Hn + tid];
    s.b1s[tid] = b1[f * Hn + tid];
    s.b2s[tid] = b2[f * Hn + tid];
  }
  if (tid >= 64 && tid < 64 + En) s.b3ps[tid - 64] = g_b3p[f * En + (tid - 64)];
  for (int i = tid; i < BM; i += 256) s.xs[i] = x[(size_t)(b0 + i) * Fn + f];
  for (int i = tid; i < Hn * Hn; i += 256) ((float*)s.W2s)[i] = W2[f * Hn * Hn + i];
  for (int i = tid; i < Hn * En; i += 256) ((float*)s.W3ps)[i] = g_W3p[f * Hn * En + i];
  __syncthreads();

  // layer 1: h1T[h][r] = leaky(x[r]*W1[h] + b1[h])
  for (int i = tid; i < Hn * BM; i += 256) {
    int h = i >> 7;          // / BM
    int r = i & (BM - 1);
    s.h1T[h][r] = leaky(fmaf(s.xs[r], s.W1s[h], s.b1s[h]));
  }
  __syncthreads();

  // layer 2: [128 rows x 64 cols], 8x4 micro-tile per thread
  {
    const int rg = tid & 15;   // row group: rows rg*8 .. rg*8+7
    const int cg = tid >> 4;   // col group: cols cg*4 .. cg*4+3
    float acc[8][4];
#pragma unroll
    for (int i = 0; i < 8; i++)
#pragma unroll
      for (int j = 0; j < 4; j++) acc[i][j] = s.b2s[cg * 4 + j];

#pragma unroll 8
    for (int k = 0; k < Hn; k++) {
      float4 a0 = *(const float4*)&s.h1T[k][rg * 8];
      float4 a1 = *(const float4*)&s.h1T[k][rg * 8 + 4];
      float4 w  = *(const float4*)&s.W2s[k][cg * 4];
      float av[8] = {a0.x, a0.y, a0.z, a0.w, a1.x, a1.y, a1.z, a1.w};
      float wv[4] = {w.x, w.y, w.z, w.w};
#pragma unroll
      for (int i = 0; i < 8; i++)
#pragma unroll
        for (int j = 0; j < 4; j++) acc[i][j] = fmaf(av[i], wv[j], acc[i][j]);
    }
#pragma unroll
    for (int j = 0; j < 4; j++) {
      float4 v0 = make_float4(leaky(acc[0][j]), leaky(acc[1][j]),
                              leaky(acc[2][j]), leaky(acc[3][j]));
      float4 v1 = make_float4(leaky(acc[4][j]), leaky(acc[5][j]),
                              leaky(acc[6][j]), leaky(acc[7][j]));
      *(float4*)&s.h2T[cg * 4 + j][rg * 8]     = v0;
      *(float4*)&s.h2T[cg * 4 + j][rg * 8 + 4] = v1;
    }
  }
  __syncthreads();

  // layer 3 (fused W3@Wp): [128 rows x 16 cols], 8 rows x 1 col per thread
  {
    const int c = tid & 15;
    const int rg = tid >> 4;   // rows rg*8 .. rg*8+7
    float acc[8];
#pragma unroll
    for (int i = 0; i < 8; i++) acc[i] = s.b3ps[c];
#pragma unroll 8
    for (int k = 0; k < Hn; k++) {
      float w = s.W3ps[k][c];
      float4 a0 = *(const float4*)&s.h2T[k][rg * 8];
      float4 a1 = *(const float4*)&s.h2T[k][rg * 8 + 4];
      acc[0] = fmaf(a0.x, w, acc[0]);
      acc[1] = fmaf(a0.y, w, acc[1]);
      acc[2] = fmaf(a0.z, w, acc[2]);
      acc[3] = fmaf(a0.w, w, acc[3]);
      acc[4] = fmaf(a1.x, w, acc[4]);
      acc[5] = fmaf(a1.y, w, acc[5]);
      acc[6] = fmaf(a1.z, w, acc[6]);
      acc[7] = fmaf(a1.w, w, acc[7]);
    }
    size_t base = (size_t)(b0 + rg * 8) * (Fn * En) + (size_t)f * En + c;
#pragma unroll
    for (int i = 0; i < 8; i++) g_tok[base + (size_t)i * (Fn * En)] = acc[i];
  }
}

// ---------------- pass 2: attention + pool + head ----------------
__global__ __launch_bounds__(128) void k_attn(
    const float* __restrict__ Wqkv, const float* __restrict__ bqkv,
    const float* __restrict__ Wo, const float* __restrict__ bo,
    const float* __restrict__ Wf, const float* __restrict__ bf,
    float* __restrict__ out) {
  __shared__ float Wq_s[En][48];
  __shared__ float bq_s[48];
  __shared__ float Wo_s[En][En];
  __shared__ float bo_s[En], Wf_s[En];
  __shared__ float bf_s;
  __shared__ float4 kv_s[8][2][En][4];   // [group][k/v][token][e/4] = 16 KB

  const int tid = threadIdx.x;
  for (int i = tid; i < En * 48; i += 128) ((float*)Wq_s)[i] = Wqkv[i];
  if (tid < 48) bq_s[tid] = bqkv[tid];
  for (int i = tid; i < En * En; i += 128) ((float*)Wo_s)[i] = Wo[i];
  if (tid < En) { bo_s[tid] = bo[tid]; Wf_s[tid] = Wf[tid]; }
  if (tid == 0) bf_s = bf[0];
  __syncthreads();

  const int g = tid >> 4;      // row group within CTA (8 rows)
  const int t = tid & 15;      // token owned by this thread
  const size_t b = (size_t)blockIdx.x * 8 + g;

  // load this token's embedding (16 floats, coalesced float4)
  float tk[16];
  {
    const float4* tp = (const float4*)(g_tok + b * (Fn * En) + (size_t)t * En);
#pragma unroll
    for (int i = 0; i < 4; i++) {
      float4 v = tp[i];
      tk[i * 4 + 0] = v.x; tk[i * 4 + 1] = v.y;
      tk[i * 4 + 2] = v.z; tk[i * 4 + 3] = v.w;
    }
  }

  // qkv = tok @ Wqkv + bqkv (this thread's token only)
  float q[16], kk[16], vv[16];
#pragma unroll
  for (int e = 0; e < 16; e++) {
    q[e]  = bq_s[e];
    kk[e] = bq_s[16 + e];
    vv[e] = bq_s[32 + e];
  }
#pragma unroll
  for (int j = 0; j < 16; j++) {
    float a = tk[j];
#pragma unroll
    for (int e = 0; e < 16; e++) {
      q[e]  = fmaf(a, Wq_s[j][e],      q[e]);
      kk[e] = fmaf(a, Wq_s[j][16 + e], kk[e]);
      vv[e] = fmaf(a, Wq_s[j][32 + e], vv[e]);
    }
  }
  // publish k, v for my token
#pragma unroll
  for (int i = 0; i < 4; i++) {
    kv_s[g][0][t][i] = make_float4(kk[i*4], kk[i*4+1], kk[i*4+2], kk[i*4+3]);
    kv_s[g][1][t][i] = make_float4(vv[i*4], vv[i*4+1], vv[i*4+2], vv[i*4+3]);
  }
  __syncwarp(0xffffffffu);

  // scores row for my query token, softmax
  float sc[16];
#pragma unroll
  for (int j = 0; j < 16; j++) {
    float acc = 0.f;
#pragma unroll
    for (int i = 0; i < 4; i++) {
      float4 kv = kv_s[g][0][j][i];
      acc += q[i*4+0] * kv.x + q[i*4+1] * kv.y + q[i*4+2] * kv.z + q[i*4+3] * kv.w;
    }
    sc[j] = acc * 0.25f;   // 1/sqrt(16)
  }
  float m = sc[0];
#pragma unroll
  for (int j = 1; j < 16; j++) m = fmaxf(m, sc[j]);
  float sum = 0.f;
#pragma unroll
  for (int j = 0; j < 16; j++) { sc[j] = expf(sc[j] - m); sum += sc[j]; }
  float inv = 1.f / sum;

  // o = softmax @ v
  float o[16];
#pragma unroll
  for (int e = 0; e < 16; e++) o[e] = 0.f;
#pragma unroll
  for (int j = 0; j < 16; j++) {
    float a = sc[j] * inv;
#pragma unroll
    for (int i = 0; i < 4; i++) {
      float4 v = kv_s[g][1][j][i];
      o[i*4+0] = fmaf(a, v.x, o[i*4+0]);
      o[i*4+1] = fmaf(a, v.y, o[i*4+1]);
      o[i*4+2] = fmaf(a, v.z, o[i*4+2]);
      o[i*4+3] = fmaf(a, v.w, o[i*4+3]);
    }
  }

  // y = o @ Wo + bo
  float y[16];
#pragma unroll
  for (int e = 0; e < 16; e++) y[e] = bo_s[e];
#pragma unroll
  for (int e2 = 0; e2 < 16; e2++) {
    float a = o[e2];
#pragma unroll
    for (int e = 0; e < 16; e++) y[e] = fmaf(a, Wo_s[e2][e], y[e]);
  }

  // mean over tokens: butterfly reduce across the 16 lanes of this group
#pragma unroll
  for (int off = 8; off; off >>= 1)
#pragma unroll
    for (int e = 0; e < 16; e++) y[e] += __shfl_xor_sync(0xffffffffu, y[e], off);

  if (t == 0) {
    float acc = bf_s;
#pragma unroll
    for (int e = 0; e < 16; e++) acc = fmaf(y[e] * (1.f / 16.f), Wf_s[e], acc);
    out[b] = leaky(acc);
  }
}

// ---------------- launch ----------------
extern "C" void kernel_launch(void* const* d_in, const int* in_sizes, int n_in,
                              void* d_out, int out_size) {
  const float* x    = (const float*)d_in[0];
  const float* W1   = (const float*)d_in[1];
  const float* b1   = (const float*)d_in[2];
  const float* W2   = (const float*)d_in[3];
  const float* b2   = (const float*)d_in[4];
  const float* W3   = (const float*)d_in[5];
  const float* b3   = (const float*)d_in[6];
  const float* Wp   = (const float*)d_in[7];
  const float* bp   = (const float*)d_in[8];
  const float* Wqkv = (const float*)d_in[9];
  const float* bqkv = (const float*)d_in[10];
  const float* Wo   = (const float*)d_in[11];
  const float* bo   = (const float*)d_in[12];
  const float* Wf   = (const float*)d_in[13];
  const float* bf   = (const float*)d_in[14];
  float* out = (float*)d_out;

  (void)in_sizes; (void)n_in; (void)out_size;

  cudaFuncSetAttribute(k_subnet, cudaFuncAttributeMaxDynamicSharedMemorySize,
                       (int)sizeof(SM1));

  k_setup<<<Fn, 128>>>(W3, b3, Wp, bp);
  dim3 g1(Bsz / BM, Fn);
  k_subnet<<<g1, 256, sizeof(SM1)>>>(x, W1, b1, W2, b2);
  k_attn<<<Bsz / 8, 128>>>(Wqkv, bqkv, Wo, bo, Wf, bf, out);
}

// round 3
// speedup vs baseline: 1.0381x; 1.0381x over previous
#include <cuda_runtime.h>
#include <math.h>

#define Bsz 32768
#define Fn 16
#define Hn 64
#define On 32
#define En 16
#define BM 128
#define LDW 140   // padded/swizzled row width for h1T/h2T (128 + 3*4)

// swizzled physical column for logical row-element r (8-float blocks, quad-rotated)
#define SWC(r) ((r) + ((((r) >> 5)) << 2))

// ---------------- device scratch (no allocations allowed) ----------------
__device__ float g_tok[(size_t)Bsz * Fn * En];   // 33.5 MB: tok[B][F][E]

// ---------------- packed f32x2 helpers ----------------
__device__ __forceinline__ float2 ffma2(float2 a, float2 b, float2 c) {
  float2 d;
  asm("fma.rn.f32x2 %0, %1, %2, %3;"
      : "=l"(*(unsigned long long*)&d)
      : "l"(*(unsigned long long*)&a),
        "l"(*(unsigned long long*)&b),
        "l"(*(unsigned long long*)&c));
  return d;
}
__device__ __forceinline__ float2 splat2(float s) { return make_float2(s, s); }
__device__ __forceinline__ float leaky(float v) { return v >= 0.f ? v : 0.01f * v; }

// ---------------- pass 1: per-feature subnet -> tok ----------------
struct __align__(16) SM1 {
  float h1T[Hn * LDW];     // 35840 B, swizzled [h][r]
  float h2T[Hn * LDW];     // 35840 B, swizzled [k][r]
  float W2s[Hn * Hn];      // 16 KB [h][k]
  float W3ps[Hn * En];     // 4 KB fused W3@Wp
  float w3raw[Hn * On];    // 8 KB
  float Wps[On * En];      // 2 KB
  float W1s[Hn], b1s[Hn], b2s[Hn];
  float b3ps[En];
  float xs[BM];
};

__global__ __launch_bounds__(256, 2) void k_subnet(
    const float* __restrict__ x, const float* __restrict__ W1,
    const float* __restrict__ b1, const float* __restrict__ W2,
    const float* __restrict__ b2, const float* __restrict__ W3,
    const float* __restrict__ b3, const float* __restrict__ Wp,
    const float* __restrict__ bp) {
  extern __shared__ char smraw[];
  SM1& s = *reinterpret_cast<SM1*>(smraw);
  const int f = blockIdx.y;
  const int b0 = blockIdx.x * BM;
  const int tid = threadIdx.x;

  // ---- load phase ----
  if (tid < Hn) {
    s.W1s[tid] = W1[f * Hn + tid];
    s.b1s[tid] = b1[f * Hn + tid];
    s.b2s[tid] = b2[f * Hn + tid];
  }
  for (int i = tid; i < BM; i += 256) s.xs[i] = x[(size_t)(b0 + i) * Fn + f];
  for (int i = tid; i < Hn * Hn; i += 256) s.W2s[i] = W2[f * Hn * Hn + i];
  for (int i = tid; i < Hn * On; i += 256) s.w3raw[i] = W3[f * Hn * On + i];
  for (int i = tid; i < On * En; i += 256) s.Wps[i] = Wp[i];
  __syncthreads();

  // ---- layer 1 (elementwise) + fold W3@Wp (independent of h1T) ----
  for (int i = tid; i < Hn * BM; i += 256) {
    int h = i >> 7, r = i & (BM - 1);
    s.h1T[h * LDW + SWC(r)] = leaky(fmaf(s.xs[r], s.W1s[h], s.b1s[h]));
  }
  for (int idx = tid; idx < Hn * En; idx += 256) {
    int h = idx >> 4, e = idx & 15;
    float acc = 0.f;
#pragma unroll 8
    for (int o = 0; o < On; o++) acc += s.w3raw[h * On + o] * s.Wps[o * En + e];
    s.W3ps[idx] = acc;
  }
  if (tid < En) {
    float acc = bp[tid];
    for (int o = 0; o < On; o++) acc += b3[f * On + o] * s.Wps[o * En + tid];
    s.b3ps[tid] = acc;
  }
  __syncthreads();

  // ---- layer 2: 128x64, thread = 8 rows x 4 cols, f32x2 packed over rows ----
  {
    const int rg = tid & 15;   // row block rg*8..rg*8+7
    const int cg = tid >> 4;   // col block cg*4..cg*4+3
    const int acol = SWC(rg * 8);

    float2 acc[4][4];
#pragma unroll
    for (int j = 0; j < 4; j++) {
      float2 bj = splat2(s.b2s[cg * 4 + j]);
#pragma unroll
      for (int i = 0; i < 4; i++) acc[i][j] = bj;
    }

#pragma unroll 8
    for (int k = 0; k < Hn; k++) {
      float4 a0 = *(const float4*)&s.h1T[k * LDW + acol];
      float4 a1 = *(const float4*)&s.h1T[k * LDW + acol + 4];
      float4 w  = *(const float4*)&s.W2s[k * Hn + cg * 4];
      float2 av[4] = {make_float2(a0.x, a0.y), make_float2(a0.z, a0.w),
                      make_float2(a1.x, a1.y), make_float2(a1.z, a1.w)};
      float2 wv[4] = {splat2(w.x), splat2(w.y), splat2(w.z), splat2(w.w)};
#pragma unroll
      for (int i = 0; i < 4; i++)
#pragma unroll
        for (int j = 0; j < 4; j++) acc[i][j] = ffma2(av[i], wv[j], acc[i][j]);
    }

#pragma unroll
    for (int j = 0; j < 4; j++) {
      float4 lo = make_float4(leaky(acc[0][j].x), leaky(acc[0][j].y),
                              leaky(acc[1][j].x), leaky(acc[1][j].y));
      float4 hi = make_float4(leaky(acc[2][j].x), leaky(acc[2][j].y),
                              leaky(acc[3][j].x), leaky(acc[3][j].y));
      *(float4*)&s.h2T[(cg * 4 + j) * LDW + acol]     = lo;
      *(float4*)&s.h2T[(cg * 4 + j) * LDW + acol + 4] = hi;
    }
  }
  __syncthreads();

  // ---- layer 3 (fused W3@Wp): 128x16, thread = 8 rows x 1 col, packed rows ----
  {
    const int c  = tid & 15;
    const int rg = tid >> 4;
    const int acol = SWC(rg * 8);

    float2 acc[4];
    {
      float2 bj = splat2(s.b3ps[c]);
#pragma unroll
      for (int i = 0; i < 4; i++) acc[i] = bj;
    }
#pragma unroll 8
    for (int k = 0; k < Hn; k++) {
      float4 a0 = *(const float4*)&s.h2T[k * LDW + acol];
      float4 a1 = *(const float4*)&s.h2T[k * LDW + acol + 4];
      float2 w2 = splat2(s.W3ps[k * En + c]);
      acc[0] = ffma2(make_float2(a0.x, a0.y), w2, acc[0]);
      acc[1] = ffma2(make_float2(a0.z, a0.w), w2, acc[1]);
      acc[2] = ffma2(make_float2(a1.x, a1.y), w2, acc[2]);
      acc[3] = ffma2(make_float2(a1.z, a1.w), w2, acc[3]);
    }
    size_t base = (size_t)(b0 + rg * 8) * (Fn * En) + (size_t)f * En + c;
    g_tok[base + 0 * (Fn * En)] = acc[0].x;
    g_tok[base + 1 * (Fn * En)] = acc[0].y;
    g_tok[base + 2 * (Fn * En)] = acc[1].x;
    g_tok[base + 3 * (Fn * En)] = acc[1].y;
    g_tok[base + 4 * (Fn * En)] = acc[2].x;
    g_tok[base + 5 * (Fn * En)] = acc[2].y;
    g_tok[base + 6 * (Fn * En)] = acc[3].x;
    g_tok[base + 7 * (Fn * En)] = acc[3].y;
  }
}

// ---------------- pass 2: attention + pool + head ----------------
__global__ __launch_bounds__(128) void k_attn(
    const float* __restrict__ Wqkv, const float* __restrict__ bqkv,
    const float* __restrict__ Wo, const float* __restrict__ bo,
    const float* __restrict__ Wf, const float* __restrict__ bf,
    float* __restrict__ out) {
  __shared__ __align__(16) float Wq_s[En][48];
  __shared__ __align__(16) float bq_s[48];
  __shared__ __align__(16) float Wo_s[En][En];
  __shared__ __align__(16) float bo_s[En], Wf_s[En];
  __shared__ float bf_s;
  __shared__ float4 kv_s[8][2][En][4];   // [group][k/v][token][e/4]

  const int tid = threadIdx.x;
  for (int i = tid; i < En * 48; i += 128) ((float*)Wq_s)[i] = Wqkv[i];
  if (tid < 48) bq_s[tid] = bqkv[tid];
  for (int i = tid; i < En * En; i += 128) ((float*)Wo_s)[i] = Wo[i];
  if (tid < En) { bo_s[tid] = bo[tid]; Wf_s[tid] = Wf[tid]; }
  if (tid == 0) bf_s = bf[0];
  __syncthreads();

  const int g = tid >> 4;
  const int t = tid & 15;
  const size_t b = (size_t)blockIdx.x * 8 + g;

  float tk[16];
  {
    const float4* tp = (const float4*)(g_tok + b * (Fn * En) + (size_t)t * En);
#pragma unroll
    for (int i = 0; i < 4; i++) {
      float4 v = tp[i];
      tk[i * 4 + 0] = v.x; tk[i * 4 + 1] = v.y;
      tk[i * 4 + 2] = v.z; tk[i * 4 + 3] = v.w;
    }
  }

  // qkv (packed over embedding pairs)
  float2 q2[8], k2[8], v2[8];
#pragma unroll
  for (int e = 0; e < 8; e++) {
    q2[e] = *(const float2*)&bq_s[2 * e];
    k2[e] = *(const float2*)&bq_s[16 + 2 * e];
    v2[e] = *(const float2*)&bq_s[32 + 2 * e];
  }
#pragma unroll
  for (int j = 0; j < 16; j++) {
    float2 aa = splat2(tk[j]);
    const float2* wrow = (const float2*)&Wq_s[j][0];
#pragma unroll
    for (int e = 0; e < 8; e++) {
      q2[e] = ffma2(aa, wrow[e],      q2[e]);
      k2[e] = ffma2(aa, wrow[8 + e],  k2[e]);
      v2[e] = ffma2(aa, wrow[16 + e], v2[e]);
    }
  }
  // publish k, v
#pragma unroll
  for (int i = 0; i < 4; i++) {
    kv_s[g][0][t][i] = make_float4(k2[2*i].x, k2[2*i].y, k2[2*i+1].x, k2[2*i+1].y);
    kv_s[g][1][t][i] = make_float4(v2[2*i].x, v2[2*i].y, v2[2*i+1].x, v2[2*i+1].y);
  }
  __syncwarp(0xffffffffu);

  // scores + softmax
  float sc[16];
#pragma unroll
  for (int j = 0; j < 16; j++) {
    float2 acc = make_float2(0.f, 0.f);
#pragma unroll
    for (int i = 0; i < 4; i++) {
      float4 kv = kv_s[g][0][j][i];
      acc = ffma2(q2[2*i],   make_float2(kv.x, kv.y), acc);
      acc = ffma2(q2[2*i+1], make_float2(kv.z, kv.w), acc);
    }
    sc[j] = (acc.x + acc.y) * 0.25f;
  }
  float m = sc[0];
#pragma unroll
  for (int j = 1; j < 16; j++) m = fmaxf(m, sc[j]);
  float sum = 0.f;
#pragma unroll
  for (int j = 0; j < 16; j++) { sc[j] = __expf(sc[j] - m); sum += sc[j]; }
  float inv = 1.f / sum;

  // o = softmax @ v  (packed)
  float2 o2[8];
#pragma unroll
  for (int e = 0; e < 8; e++) o2[e] = make_float2(0.f, 0.f);
#pragma unroll
  for (int j = 0; j < 16; j++) {
    float2 a2 = splat2(sc[j] * inv);
#pragma unroll
    for (int i = 0; i < 4; i++) {
      float4 v = kv_s[g][1][j][i];
      o2[2*i]   = ffma2(a2, make_float2(v.x, v.y), o2[2*i]);
      o2[2*i+1] = ffma2(a2, make_float2(v.z, v.w), o2[2*i+1]);
    }
  }

  // y = o @ Wo + bo  (packed)
  float2 y2[8];
#pragma unroll
  for (int e = 0; e < 8; e++) y2[e] = *(const float2*)&bo_s[2 * e];
  float ov[16];
#pragma unroll
  for (int e = 0; e < 8; e++) { ov[2*e] = o2[e].x; ov[2*e+1] = o2[e].y; }
#pragma unroll
  for (int e2 = 0; e2 < 16; e2++) {
    float2 a2 = splat2(ov[e2]);
    const float2* wrow = (const float2*)&Wo_s[e2][0];
#pragma unroll
    for (int e = 0; e < 8; e++) y2[e] = ffma2(a2, wrow[e], y2[e]);
  }

  // mean over tokens: butterfly across the 16 lanes of this group
  float y[16];
#pragma unroll
  for (int e = 0; e < 8; e++) { y[2*e] = y2[e].x; y[2*e+1] = y2[e].y; }
#pragma unroll
  for (int off = 8; off; off >>= 1)
#pragma unroll
    for (int e = 0; e < 16; e++) y[e] += __shfl_xor_sync(0xffffffffu, y[e], off);

  if (t == 0) {
    float acc = bf_s;
#pragma unroll
    for (int e = 0; e < 16; e++) acc = fmaf(y[e] * (1.f / 16.f), Wf_s[e], acc);
    out[b] = leaky(acc);
  }
}

// ---------------- launch ----------------
extern "C" void kernel_launch(void* const* d_in, const int* in_sizes, int n_in,
                              void* d_out, int out_size) {
  const float* x    = (const float*)d_in[0];
  const float* W1   = (const float*)d_in[1];
  const float* b1   = (const float*)d_in[2];
  const float* W2   = (const float*)d_in[3];
  const float* b2   = (const float*)d_in[4];
  const float* W3   = (const float*)d_in[5];
  const float* b3   = (const float*)d_in[6];
  const float* Wp   = (const float*)d_in[7];
  const float* bp   = (const float*)d_in[8];
  const float* Wqkv = (const float*)d_in[9];
  const float* bqkv = (const float*)d_in[10];
  const float* Wo   = (const float*)d_in[11];
  const float* bo   = (const float*)d_in[12];
  const float* Wf   = (const float*)d_in[13];
  const float* bf   = (const float*)d_in[14];
  float* out = (float*)d_out;

  (void)in_sizes; (void)n_in; (void)out_size;

  cudaFuncSetAttribute(k_subnet, cudaFuncAttributeMaxDynamicSharedMemorySize,
                       (int)sizeof(SM1));

  dim3 g1(Bsz / BM, Fn);
  k_subnet<<<g1, 256, sizeof(SM1)>>>(x, W1, b1, W2, b2, W3, b3, Wp, bp);
  k_attn<<<Bsz / 8, 128>>>(Wqkv, bqkv, Wo, bo, Wf, bf, out);
}

// round 5
// speedup vs baseline: 2.3799x; 2.2926x over previous
#include <cuda_runtime.h>
#include <cuda_bf16.h>
#include <math.h>
#include <stdint.h>

#define Bsz 32768
#define Fn 16
#define Hn 64
#define On 32
#define En 16
#define BM 128
#define TILES 8
#define GRPS 32          // GRPS*TILES*BM = 32768
#define HP 36            // uint32 pitch for h buffers (36 = 4 mod 32 -> conflict-free)

// ---------------- device scratch ----------------
__device__ float g_tok[(size_t)Bsz * Fn * En];   // tok[B][F][E]

// ---------------- constants for attention ----------------
__constant__ float cWqkv[En * 48];
__constant__ float cbqkv[48];
__constant__ float cWo[En * En];
__constant__ float cbo[En];
__constant__ float cWf[En];
__constant__ float cbf[1];

// ---------------- helpers ----------------
__device__ __forceinline__ float leaky(float v) { return v >= 0.f ? v : 0.01f * v; }
__device__ __forceinline__ float2 splat2(float s) { return make_float2(s, s); }
__device__ __forceinline__ float2 ffma2(float2 a, float2 b, float2 c) {
  float2 d;
  asm("fma.rn.f32x2 %0, %1, %2, %3;"
      : "=l"(*(unsigned long long*)&d)
      : "l"(*(unsigned long long*)&a), "l"(*(unsigned long long*)&b),
        "l"(*(unsigned long long*)&c));
  return d;
}

// pack two floats as bf16x2 (lo element in low half)
__device__ __forceinline__ uint32_t bfpack(float lo, float hi) {
  uint32_t r;
  asm("cvt.rn.bf16x2.f32 %0, %1, %2;" : "=r"(r) : "f"(hi), "f"(lo));
  return r;
}
// 2-way bf16 split of a float pair
__device__ __forceinline__ void split_pair(float v0, float v1, uint32_t& hi, uint32_t& lo) {
  float h0 = __bfloat162float(__float2bfloat16(v0));
  float h1 = __bfloat162float(__float2bfloat16(v1));
  hi = bfpack(h0, h1);
  lo = bfpack(v0 - h0, v1 - h1);
}

__device__ __forceinline__ void mma_bf16(float* c, uint32_t a0, uint32_t a1, uint32_t a2,
                                         uint32_t a3, uint32_t b0, uint32_t b1) {
  asm volatile(
      "mma.sync.aligned.m16n8k16.row.col.f32.bf16.bf16.f32 "
      "{%0,%1,%2,%3}, {%4,%5,%6,%7}, {%8,%9}, {%0,%1,%2,%3};"
      : "+f"(c[0]), "+f"(c[1]), "+f"(c[2]), "+f"(c[3])
      : "r"(a0), "r"(a1), "r"(a2), "r"(a3), "r"(b0), "r"(b1));
}

// ---------------- pass 1 smem ----------------
struct __align__(16) SM {
  uint32_t hHi[BM * HP];     // 18432 B  packed bf16x2 (hi)
  uint32_t hLo[BM * HP];     // 18432 B  (lo)
  uint32_t w3Hi[En * HP];    // 2304 B   W3p pairs [n][kp]
  uint32_t w3Lo[En * HP];    // 2304 B
  float W1s[Hn], b1s[Hn], b2s[Hn];
  float b3ps[En];
  float w3tmp[Hn * En];      // 4096 B
};

__global__ __launch_bounds__(128) void k_subnet(
    const float* __restrict__ x, const float* __restrict__ W1,
    const float* __restrict__ b1, const float* __restrict__ W2,
    const float* __restrict__ b2, const float* __restrict__ W3,
    const float* __restrict__ b3, const float* __restrict__ Wp,
    const float* __restrict__ bp) {
  extern __shared__ char smraw[];
  SM& s = *reinterpret_cast<SM*>(smraw);
  const int tid = threadIdx.x;
  const int lane = tid & 31;
  const int wid = tid >> 5;
  const int f = blockIdx.x;
  const int grp = blockIdx.y;
  const int q = lane >> 2;   // 0..7
  const int l3 = lane & 3;   // 0..3

  // ---- per-CTA init ----
  if (tid < Hn) {
    s.W1s[tid] = W1[f * Hn + tid];
    s.b1s[tid] = b1[f * Hn + tid];
    s.b2s[tid] = b2[f * Hn + tid];
  }
  if (tid < En) {
    float acc = bp[tid];
    for (int o = 0; o < On; o++) acc += b3[f * On + o] * Wp[o * En + tid];
    s.b3ps[tid] = acc;
  }
  for (int i = tid; i < Hn * En; i += 128) {
    int h = i >> 4, e = i & 15;
    float acc = 0.f;
#pragma unroll 8
    for (int o = 0; o < On; o++) acc += W3[f * Hn * On + h * On + o] * Wp[o * En + e];
    s.w3tmp[i] = acc;
  }

  // W2 B-fragments into registers (loop-invariant). [nt*4+s][b01]
  uint32_t B2h[8][2], B2l[8][2];
  {
    const float* W2g = W2 + (size_t)f * Hn * Hn;
    const int n = wid * 16 + (q);  // + nt*8 added below
#pragma unroll
    for (int nt = 0; nt < 2; nt++)
#pragma unroll
      for (int sstep = 0; sstep < 4; sstep++) {
        int nn = n + nt * 8;
        int k0 = sstep * 16 + 2 * l3;
        split_pair(W2g[k0 * Hn + nn], W2g[(k0 + 1) * Hn + nn],
                   B2h[nt * 4 + sstep][0], B2l[nt * 4 + sstep][0]);
        split_pair(W2g[(k0 + 8) * Hn + nn], W2g[(k0 + 9) * Hn + nn],
                   B2h[nt * 4 + sstep][1], B2l[nt * 4 + sstep][1]);
      }
  }
  __syncthreads();

  // pack W3p as split bf16x2 pairs: [n][kp], kp = k/2
  for (int i = tid; i < En * 32; i += 128) {
    int n = i >> 5, kp = i & 31;
    split_pair(s.w3tmp[(2 * kp) * En + n], s.w3tmp[(2 * kp + 1) * En + n],
               s.w3Hi[n * HP + kp], s.w3Lo[n * HP + kp]);
  }
  __syncthreads();

  const int tile0 = grp * TILES;
  float xv = x[(size_t)(tile0 * BM + tid) * Fn + f];

  for (int t = 0; t < TILES; t++) {
    const int b0row = (tile0 + t) * BM;

    // ---- layer 1: h1 row tid (64 values), split-packed into smem ----
#pragma unroll
    for (int kb = 0; kb < 16; kb++) {
      float4 w = ((const float4*)s.W1s)[kb];
      float4 bb = ((const float4*)s.b1s)[kb];
      float v0 = leaky(fmaf(xv, w.x, bb.x));
      float v1 = leaky(fmaf(xv, w.y, bb.y));
      float v2 = leaky(fmaf(xv, w.z, bb.z));
      float v3 = leaky(fmaf(xv, w.w, bb.w));
      split_pair(v0, v1, s.hHi[tid * HP + kb * 2], s.hLo[tid * HP + kb * 2]);
      split_pair(v2, v3, s.hHi[tid * HP + kb * 2 + 1], s.hLo[tid * HP + kb * 2 + 1]);
    }
    if (t + 1 < TILES)
      xv = x[(size_t)(b0row + BM + tid) * Fn + f];   // prefetch next tile's x
    __syncthreads();

    // ---- layer 2: C[128,64] = h1 @ W2, warp owns N=16 ----
    float C[8][2][4];
#pragma unroll
    for (int mt = 0; mt < 8; mt++)
#pragma unroll
      for (int nt = 0; nt < 2; nt++)
#pragma unroll
        for (int i = 0; i < 4; i++) C[mt][nt][i] = 0.f;

#pragma unroll
    for (int mt = 0; mt < 8; mt++) {
      const int r0 = mt * 16 + q;
#pragma unroll
      for (int sstep = 0; sstep < 4; sstep++) {
        const int ai = sstep * 8 + l3;
        uint32_t a0h = s.hHi[r0 * HP + ai],       a1h = s.hHi[(r0 + 8) * HP + ai];
        uint32_t a2h = s.hHi[r0 * HP + ai + 4],   a3h = s.hHi[(r0 + 8) * HP + ai + 4];
        uint32_t a0l = s.hLo[r0 * HP + ai],       a1l = s.hLo[(r0 + 8) * HP + ai];
        uint32_t a2l = s.hLo[r0 * HP + ai + 4],   a3l = s.hLo[(r0 + 8) * HP + ai + 4];
#pragma unroll
        for (int nt = 0; nt < 2; nt++) {
          mma_bf16(C[mt][nt], a0h, a1h, a2h, a3h, B2h[nt * 4 + sstep][0], B2h[nt * 4 + sstep][1]);
          mma_bf16(C[mt][nt], a0h, a1h, a2h, a3h, B2l[nt * 4 + sstep][0], B2l[nt * 4 + sstep][1]);
          mma_bf16(C[mt][nt], a0l, a1l, a2l, a3l, B2h[nt * 4 + sstep][0], B2h[nt * 4 + sstep][1]);
        }
      }
    }
    __syncthreads();   // all h1 reads done before overwriting with h2

    // ---- epilogue 2: h2 = leaky(C + b2), split-pack back into h buffers ----
#pragma unroll
    for (int mt = 0; mt < 8; mt++) {
      const int r0 = mt * 16 + q;
#pragma unroll
      for (int nt = 0; nt < 2; nt++) {
        const int n0 = wid * 16 + nt * 8 + 2 * l3;
        const int ci = wid * 8 + nt * 4 + l3;    // n0/2
        float v0 = leaky(C[mt][nt][0] + s.b2s[n0]);
        float v1 = leaky(C[mt][nt][1] + s.b2s[n0 + 1]);
        split_pair(v0, v1, s.hHi[r0 * HP + ci], s.hLo[r0 * HP + ci]);
        float v2 = leaky(C[mt][nt][2] + s.b2s[n0]);
        float v3 = leaky(C[mt][nt][3] + s.b2s[n0 + 1]);
        split_pair(v2, v3, s.hHi[(r0 + 8) * HP + ci], s.hLo[(r0 + 8) * HP + ci]);
      }
    }
    __syncthreads();

    // ---- layer 3: D[128,16] = h2 @ W3p, warp owns M=32 ----
    float C3[2][2][4];
#pragma unroll
    for (int mt2 = 0; mt2 < 2; mt2++)
#pragma unroll
      for (int nt = 0; nt < 2; nt++)
#pragma unroll
        for (int i = 0; i < 4; i++) C3[mt2][nt][i] = 0.f;

#pragma unroll
    for (int mt2 = 0; mt2 < 2; mt2++) {
      const int r0 = wid * 32 + mt2 * 16 + q;
#pragma unroll
      for (int sstep = 0; sstep < 4; sstep++) {
        const int ai = sstep * 8 + l3;
        uint32_t a0h = s.hHi[r0 * HP + ai],       a1h = s.hHi[(r0 + 8) * HP + ai];
        uint32_t a2h = s.hHi[r0 * HP + ai + 4],   a3h = s.hHi[(r0 + 8) * HP + ai + 4];
        uint32_t a0l = s.hLo[r0 * HP + ai],       a1l = s.hLo[(r0 + 8) * HP + ai];
        uint32_t a2l = s.hLo[r0 * HP + ai + 4],   a3l = s.hLo[(r0 + 8) * HP + ai + 4];
        const int kb = l3 + sstep * 8;
#pragma unroll
        for (int nt = 0; nt < 2; nt++) {
          const int nn = nt * 8 + q;
          uint32_t b0h = s.w3Hi[nn * HP + kb], b1h = s.w3Hi[nn * HP + kb + 4];
          uint32_t b0l = s.w3Lo[nn * HP + kb], b1l = s.w3Lo[nn * HP + kb + 4];
          mma_bf16(C3[mt2][nt], a0h, a1h, a2h, a3h, b0h, b1h);
          mma_bf16(C3[mt2][nt], a0h, a1h, a2h, a3h, b0l, b1l);
          mma_bf16(C3[mt2][nt], a0l, a1l, a2l, a3l, b0h, b1h);
        }
      }
    }

    // ---- epilogue 3: + b3p, store to g_tok ----
#pragma unroll
    for (int mt2 = 0; mt2 < 2; mt2++) {
      const int r0 = wid * 32 + mt2 * 16 + q;
#pragma unroll
      for (int nt = 0; nt < 2; nt++) {
        const int n0 = nt * 8 + 2 * l3;
        float2 d0 = make_float2(C3[mt2][nt][0] + s.b3ps[n0], C3[mt2][nt][1] + s.b3ps[n0 + 1]);
        float2 d1 = make_float2(C3[mt2][nt][2] + s.b3ps[n0], C3[mt2][nt][3] + s.b3ps[n0 + 1]);
        *(float2*)&g_tok[(size_t)(b0row + r0) * (Fn * En) + f * En + n0] = d0;
        *(float2*)&g_tok[(size_t)(b0row + r0 + 8) * (Fn * En) + f * En + n0] = d1;
      }
    }
    __syncthreads();   // h buffers reused as h1 next tile
  }
}

// ---------------- pass 2: attention (weights in __constant__) ----------------
__global__ __launch_bounds__(128) void k_attn(float* __restrict__ out) {
  __shared__ float4 kv_s[8][2][En][4];   // [group][k/v][token][e/4]

  const int tid = threadIdx.x;
  const int g = tid >> 4;
  const int t = tid & 15;
  const size_t b = (size_t)blockIdx.x * 8 + g;

  float tk[16];
  {
    const float4* tp = (const float4*)(g_tok + b * (Fn * En) + (size_t)t * En);
#pragma unroll
    for (int i = 0; i < 4; i++) {
      float4 v = tp[i];
      tk[i * 4 + 0] = v.x; tk[i * 4 + 1] = v.y;
      tk[i * 4 + 2] = v.z; tk[i * 4 + 3] = v.w;
    }
  }

  // qkv = tok @ Wqkv + bqkv (weights via constant cache, warp-uniform addrs)
  float2 q2[8], k2[8], v2[8];
#pragma unroll
  for (int e = 0; e < 8; e++) {
    q2[e] = *(const float2*)&cbqkv[2 * e];
    k2[e] = *(const float2*)&cbqkv[16 + 2 * e];
    v2[e] = *(const float2*)&cbqkv[32 + 2 * e];
  }
#pragma unroll
  for (int j = 0; j < 16; j++) {
    float2 aa = splat2(tk[j]);
    const float2* wrow = (const float2*)&cWqkv[j * 48];
#pragma unroll
    for (int e = 0; e < 8; e++) {
      q2[e] = ffma2(aa, wrow[e], q2[e]);
      k2[e] = ffma2(aa, wrow[8 + e], k2[e]);
      v2[e] = ffma2(aa, wrow[16 + e], v2[e]);
    }
  }
#pragma unroll
  for (int i = 0; i < 4; i++) {
    kv_s[g][0][t][i] = make_float4(k2[2*i].x, k2[2*i].y, k2[2*i+1].x, k2[2*i+1].y);
    kv_s[g][1][t][i] = make_float4(v2[2*i].x, v2[2*i].y, v2[2*i+1].x, v2[2*i+1].y);
  }
  __syncwarp(0xffffffffu);

  float sc[16];
#pragma unroll
  for (int j = 0; j < 16; j++) {
    float2 acc = make_float2(0.f, 0.f);
#pragma unroll
    for (int i = 0; i < 4; i++) {
      float4 kv = kv_s[g][0][j][i];
      acc = ffma2(q2[2*i], make_float2(kv.x, kv.y), acc);
      acc = ffma2(q2[2*i+1], make_float2(kv.z, kv.w), acc);
    }
    sc[j] = (acc.x + acc.y) * 0.25f;
  }
  float mx = sc[0];
#pragma unroll
  for (int j = 1; j < 16; j++) mx = fmaxf(mx, sc[j]);
  float sum = 0.f;
#pragma unroll
  for (int j = 0; j < 16; j++) { sc[j] = __expf(sc[j] - mx); sum += sc[j]; }
  float inv = 1.f / sum;

  float2 o2[8];
#pragma unroll
  for (int e = 0; e < 8; e++) o2[e] = make_float2(0.f, 0.f);
#pragma unroll
  for (int j = 0; j < 16; j++) {
    float2 a2 = splat2(sc[j] * inv);
#pragma unroll
    for (int i = 0; i < 4; i++) {
      float4 v = kv_s[g][1][j][i];
      o2[2*i] = ffma2(a2, make_float2(v.x, v.y), o2[2*i]);
      o2[2*i+1] = ffma2(a2, make_float2(v.z, v.w), o2[2*i+1]);
    }
  }

  float2 y2[8];
#pragma unroll
  for (int e = 0; e < 8; e++) y2[e] = *(const float2*)&cbo[2 * e];
  float ov[16];
#pragma unroll
  for (int e = 0; e < 8; e++) { ov[2*e] = o2[e].x; ov[2*e+1] = o2[e].y; }
#pragma unroll
  for (int e2 = 0; e2 < 16; e2++) {
    float2 a2 = splat2(ov[e2]);
    const float2* wrow = (const float2*)&cWo[e2 * 16];
#pragma unroll
    for (int e = 0; e < 8; e++) y2[e] = ffma2(a2, wrow[e], y2[e]);
  }

  float y[16];
#pragma unroll
  for (int e = 0; e < 8; e++) { y[2*e] = y2[e].x; y[2*e+1] = y2[e].y; }
#pragma unroll
  for (int off = 8; off; off >>= 1)
#pragma unroll
    for (int e = 0; e < 16; e++) y[e] += __shfl_xor_sync(0xffffffffu, y[e], off);

  if (t == 0) {
    float acc = cbf[0];
#pragma unroll
    for (int e = 0; e < 16; e++) acc = fmaf(y[e] * (1.f / 16.f), cWf[e], acc);
    out[b] = leaky(acc);
  }
}

__global__ void k_nop() {}

// ---------------- launch ----------------
extern "C" void kernel_launch(void* const* d_in, const int* in_sizes, int n_in,
                              void* d_out, int out_size) {
  const float* x    = (const float*)d_in[0];
  const float* W1   = (const float*)d_in[1];
  const float* b1   = (const float*)d_in[2];
  const float* W2   = (const float*)d_in[3];
  const float* b2   = (const float*)d_in[4];
  const float* W3   = (const float*)d_in[5];
  const float* b3   = (const float*)d_in[6];
  const float* Wp   = (const float*)d_in[7];
  const float* bp   = (const float*)d_in[8];
  const float* Wqkv = (const float*)d_in[9];
  const float* bqkv = (const float*)d_in[10];
  const float* Wo   = (const float*)d_in[11];
  const float* bo   = (const float*)d_in[12];
  const float* Wf   = (const float*)d_in[13];
  const float* bf   = (const float*)d_in[14];
  float* out = (float*)d_out;

  (void)in_sizes; (void)n_in; (void)out_size;

  // attention weights -> constant memory (D2D async, graph-capturable)
  cudaMemcpyToSymbolAsync(cWqkv, Wqkv, En * 48 * sizeof(float), 0, cudaMemcpyDeviceToDevice, 0);
  cudaMemcpyToSymbolAsync(cbqkv, bqkv, 48 * sizeof(float), 0, cudaMemcpyDeviceToDevice, 0);
  cudaMemcpyToSymbolAsync(cWo, Wo, En * En * sizeof(float), 0, cudaMemcpyDeviceToDevice, 0);
  cudaMemcpyToSymbolAsync(cbo, bo, En * sizeof(float), 0, cudaMemcpyDeviceToDevice, 0);
  cudaMemcpyToSymbolAsync(cWf, Wf, En * sizeof(float), 0, cudaMemcpyDeviceToDevice, 0);
  cudaMemcpyToSymbolAsync(cbf, bf, sizeof(float), 0, cudaMemcpyDeviceToDevice, 0);

  cudaFuncSetAttribute(k_subnet, cudaFuncAttributeMaxDynamicSharedMemorySize,
                       (int)sizeof(SM));

  k_nop<<<1, 1>>>();
  dim3 g1(Fn, GRPS);
  k_subnet<<<g1, 128, sizeof(SM)>>>(x, W1, b1, W2, b2, W3, b3, Wp, bp);
  k_attn<<<Bsz / 8, 128>>>(out);
  k_nop<<<1, 1>>>();   // 4 kernel launches/iter -> ncu (-s 5 -c 1) lands on k_subnet
}